// round 9
// baseline (speedup 1.0000x reference)
#include <cuda_runtime.h>
#include <math.h>
#include <float.h>

#define Bb 8
#define Tt 256
#define NPOS (Bb*Tt)     // 2048
#define IDIM 80
#define HDIM 256
#define CDIM 64
#define NIT 4
#define TPB 512
#define NSHIFT 159
#define NSENC 81
#define ETH_I 40
#define NW 16            // warps per CTA

typedef unsigned long long u64;

__device__ float g_partial[NPOS];
__device__ float g_gram[80 * 160];   // u>=1 rows PRE-DOUBLED; zero-padded beyond 160-u
__device__ float g_bcv[160];
__device__ float g_cbe;
__device__ float g_G2[113 * 512];    // access-order transposed gram stream (row 112 = pad)

// ---------------- f32x2 helpers ----------------
__device__ __forceinline__ u64 dup2(float x) {
    u64 r; asm("mov.b64 %0, {%1, %1};" : "=l"(r) : "f"(x)); return r;
}
__device__ __forceinline__ u64 pack2(float lo, float hi) {
    u64 r; asm("mov.b64 %0, {%1, %2};" : "=l"(r) : "f"(lo), "f"(hi)); return r;
}
__device__ __forceinline__ void fma2(u64& acc, u64 a, u64 b) {
    asm("fma.rn.f32x2 %0, %1, %2, %0;" : "+l"(acc) : "l"(a), "l"(b));
}
__device__ __forceinline__ void unpk(u64 v, float& lo, float& hi) {
    asm("mov.b64 {%0, %1}, %2;" : "=f"(lo), "=f"(hi) : "l"(v));
}

// ---------------- reductions (deterministic; zeros appended keep bits) ----------------
__device__ __forceinline__ float warpSum(float v) {
#pragma unroll
    for (int o = 16; o > 0; o >>= 1) v += __shfl_down_sync(0xffffffffu, v, o);
    return v;
}

__device__ __forceinline__ float blockSum(float v, float* buf) {
    v = warpSum(v);
    int w = threadIdx.x >> 5, l = threadIdx.x & 31;
    if (l == 0) buf[w] = v;
    __syncthreads();
    float s = 0.f;
#pragma unroll
    for (int i = 0; i < NW; i++) s += buf[i];
    __syncthreads();
    return s;
}

__device__ __forceinline__ float blockMax(float v, float* buf) {
#pragma unroll
    for (int o = 16; o > 0; o >>= 1) v = fmaxf(v, __shfl_down_sync(0xffffffffu, v, o));
    int w = threadIdx.x >> 5, l = threadIdx.x & 31;
    if (l == 0) buf[w] = v;
    __syncthreads();
    float s = buf[0];
#pragma unroll
    for (int i = 1; i < NW; i++) s = fmaxf(s, buf[i]);
    __syncthreads();
    return s;
}

__device__ __forceinline__ int blockArgmax(const float* arr, int L, float* fb, int* ib) {
    float bv = -FLT_MAX; int bi = 0x7FFFFFFF;
    for (int i = threadIdx.x; i < L; i += TPB) {
        float v = arr[i];
        if (v > bv || (v == bv && i < bi)) { bv = v; bi = i; }
    }
#pragma unroll
    for (int o = 16; o > 0; o >>= 1) {
        float ov = __shfl_down_sync(0xffffffffu, bv, o);
        int   oi = __shfl_down_sync(0xffffffffu, bi, o);
        if (ov > bv || (ov == bv && oi < bi)) { bv = ov; bi = oi; }
    }
    int w = threadIdx.x >> 5, l = threadIdx.x & 31;
    if (l == 0) { fb[w] = bv; ib[w] = bi; }
    __syncthreads();
    float v = fb[0]; int j = ib[0];
#pragma unroll
    for (int i = 1; i < NW; i++)
        if (fb[i] > v || (fb[i] == v && ib[i] < j)) { v = fb[i]; j = ib[i]; }
    __syncthreads();
    return j;
}

// ---------------- alignment ----------------
__device__ __forceinline__ int align_fn(const float* xpad, const float* yr, float ny,
                                        float* sim, float* yal, float* fb, int* ib) {
    int s = threadIdx.x;
    if (s < NSHIFT) {
        float num = 0.f, nx2 = 0.f;
        const float* xp = xpad + s + 1;
#pragma unroll 8
        for (int w = 0; w < 80; w++) {
            float xv = xp[w];
            num = fmaf(xv, yr[w], num);
            nx2 = fmaf(xv, xv, nx2);
        }
        sim[s] = num / (sqrtf(nx2) * ny + 1e-6f);
    }
    __syncthreads();
    int theta = blockArgmax(sim, NSHIFT, fb, ib);
    if (threadIdx.x < IDIM)
        yal[threadIdx.x] = xpad[theta + (int)threadIdx.x + 1];
    __syncthreads();
    return theta;
}

// ---------------- corr segment: 8 paired-t accumulators (FFMA2) ----------------
// per-lane FMA order identical to the validated scalar order.
__device__ __forceinline__ void enc_seg8(const float* inp, const float* ipu,
                                         const float* __restrict__ gbase, int joff,
                                         u64* acc2, int nblocks) {
    const float* gp = gbase + joff * 512;
    u64 E[4], O[4];
    float c;
    {   // init window: rows joff..joff+8 (9 reads)
        float prev = *gp; gp += 512;
#pragma unroll
        for (int k = 0; k < 4; k++) {
            float a = *gp; gp += 512;
            float b = *gp; gp += 512;
            E[k] = pack2(prev, a);
            O[k] = pack2(a, b);
            prev = b;
        }
        c = prev;
    }
    for (int b = 0; b < nblocks; b++) {
        const float* ia = inp + (b << 4);
        const float* ib2 = ipu + (b << 4);
#pragma unroll
        for (int i = 0; i < 16; i++) {
            float qv = ia[i] * ib2[i];
            u64 qd = dup2(qv);
            if ((i & 1) == 0) {
#pragma unroll
                for (int m = 0; m < 4; m++)
                    fma2(acc2[m], qd, E[((i >> 1) + m) & 3]);
                float n = *gp; gp += 512;
                E[(i >> 1) & 3] = pack2(c, n);
                c = n;
            } else {
#pragma unroll
                for (int m = 0; m < 4; m++)
                    fma2(acc2[m], qd, O[((i >> 1) + m) & 3]);
                float n = *gp; gp += 512;
                O[(i >> 1) & 3] = pack2(c, n);
                c = n;
            }
        }
    }
}

// ---------------- encoder via Gram energies ----------------
__device__ __noinline__ int encode_fn(const float* __restrict__ We,
                                      const float* __restrict__ be,
                                      const float* inp, float* part, float* lin,
                                      float* s_h, float* en, float cbe,
                                      float* fb, int* ib) {
    int tid = threadIdx.x;

    if (tid < 400) {
        // pair-chunk item: pair p (lags u=p, u2=79-p), t-chunk t0 = 8*cch
        int p = tid / 10, cch = tid - 10 * p;
        int u = p, u2 = 79 - p;
        int P1 = ((95 - u) >> 4) << 4;
        u64 acc2[4];
#pragma unroll
        for (int m = 0; m < 4; m++) acc2[m] = 0ull;
        const float* gbase = g_G2 + tid;
        enc_seg8(inp, inp + u,  gbase, 0,      acc2, P1 >> 4);
        enc_seg8(inp, inp + u2, gbase, P1 + 8, acc2, (96 - P1) >> 4);
        float* pp = part + p * 81 + (cch << 3);
#pragma unroll
        for (int m = 0; m < 4; m++) {
            float lo, hi; unpk(acc2[m], lo, hi);
            pp[2 * m]     = lo;
            pp[2 * m + 1] = hi;
        }
    } else if (tid < 440) {
        // scalar item: t = 80 for pair p
        int p = tid - 400;
        int u = p, u2 = 79 - p;
        int P1 = ((95 - u) >> 4) << 4;
        int P2 = 96 - P1;
        const float* gp = g_G2 + tid;
        float a = 0.f;
        {
            const float* ipu = inp + u;
            for (int d = 0; d < P1; d++) { a = fmaf(inp[d] * ipu[d], *gp, a); gp += 512; }
        }
        {
            const float* ipu = inp + u2;
            for (int d = 0; d < P2; d++) { a = fmaf(inp[d] * ipu[d], *gp, a); gp += 512; }
        }
        part[p * 81 + 80] = a;
    } else {
        // bias-linear terms (threads 440..511): t = k, plus t = 72+k for k<9
        int k = tid - 440;
#pragma unroll
        for (int rep = 0; rep < 2; rep++) {
            int t = k + rep * 72;
            if (t < 81) {
                float l = 0.f;
                const float* bc = g_bcv + t;
#pragma unroll 4
                for (int d = 0; d < 80; d++) l = fmaf(inp[d], bc[d], l);
                lin[t] = l;
            }
        }
    }
    __syncthreads();

    if (tid <= 80) {
        int t = tid;
        float s = 0.f;
#pragma unroll 4
        for (int p = 0; p < 40; p++) s += part[p * 81 + t];
        en[80 - t] = cbe + 2.f * lin[t] + s;
    }
    __syncthreads();

    int ind = blockArgmax(en, NSENC, fb, ib);

    // recompute H[ind] exactly (validated FMA order)
    if (tid < HDIM) {
        const float* wp = We + (80 - ind) * 256 + tid;
        float a0 = 0.f, a1 = 0.f, a2 = 0.f, a3 = 0.f;
#pragma unroll 4
        for (int d = 0; d < 80; d += 4) {
            a0 = fmaf(inp[d],     wp[(d)     * 256], a0);
            a1 = fmaf(inp[d + 1], wp[(d + 1) * 256], a1);
            a2 = fmaf(inp[d + 2], wp[(d + 2) * 256], a2);
            a3 = fmaf(inp[d + 3], wp[(d + 3) * 256], a3);
        }
        s_h[tid] = be[tid] + ((a0 + a1) + (a2 + a3));
    }
    __syncthreads();
    return ind;
}

// ---------------- HSR via warp-sorted rank ----------------
__device__ __forceinline__ u64 warp_sort32(u64 key) {
    int lane = threadIdx.x & 31;
#pragma unroll
    for (int k = 2; k <= 32; k <<= 1) {
#pragma unroll
        for (int j = k >> 1; j > 0; j >>= 1) {
            u64 other = __shfl_xor_sync(0xffffffffu, key, j);
            bool up = ((lane & k) == 0);
            bool lower = ((lane & j) == 0);
            bool takeMin = (up == lower);
            u64 mn = (key < other) ? key : other;
            u64 mx = (key < other) ? other : key;
            key = takeMin ? mn : mx;
        }
    }
    return key;
}

__device__ __forceinline__ int rank_sorted(u64 key, const u64* lists) {
    int cle = 0;
#pragma unroll
    for (int w = 0; w < 8; w++) {
        const u64* L = lists + (w << 5);
        int cnt = 0;
#pragma unroll
        for (int step = 16; step > 0; step >>= 1) {
            int t = cnt + step;
            if (t <= 32 && L[t - 1] <= key) cnt = t;
        }
        if (cnt < 32 && L[cnt] <= key) cnt++;
        cle += cnt;
    }
    return 256 - cle;
}

__device__ __forceinline__ u64 make_key(float hq, int tid) {
    return ((u64)__float_as_uint(hq) << 32) | (u64)(unsigned)(255 - (tid & 255));
}

__device__ __forceinline__ float hsr_fn(const float* hin, float* mp, bool first, bool smt,
                                        u64* lists, float* wred, float2* cpk, int* ibuf) {
    int tid = threadIdx.x, lane = tid & 31, wid = tid >> 5;
    bool act = (tid < HDIM);            // warps 0..7 exactly
    float h = act ? hin[tid] : 0.f;
    u64 key = make_key(h * h, tid);
    if (act) {
        u64 skey = warp_sort32(key);
        lists[(wid << 5) + lane] = skey;
    }
    __syncthreads();
    bool cur = act ? (rank_sorted(key, lists) < CDIM) : false;
    float loss = 0.f;
    bool sel = false; float hval = 0.f;
    if (first) {
        if (act) mp[tid] = cur ? 1.f : 0.f;
        sel = cur; hval = h;
        __syncthreads();
    } else {
        bool prev = act ? (mp[tid] > 0.f) : false;
        loss = blockSum((prev && cur && !smt) ? h * h : 0.f, wred);   // syncs inside
        float h2 = prev ? 0.f : h;
        u64 key2 = make_key(h2 * h2, tid);
        if (act) {
            u64 skey2 = warp_sort32(key2);
            lists[(wid << 5) + lane] = skey2;
        }
        __syncthreads();
        bool cur2 = act ? (rank_sorted(key2, lists) < CDIM) : false;
        if (act && cur2) mp[tid] += 1.f;
        sel = cur2; hval = h2;
    }
    unsigned bal = __ballot_sync(0xffffffffu, sel);
    if (lane == 0) ibuf[wid] = __popc(bal);
    __syncthreads();
    int base = 0;
#pragma unroll
    for (int w = 0; w < NW; w++) base += (w < wid) ? ibuf[w] : 0;
    int pos = base + __popc(bal & ((1u << lane) - 1u));
    if (sel) cpk[pos] = make_float2(hval, __int_as_float(tid * 160));
    __syncthreads();
    return loss;
}

// ---------------- sparse decode ----------------
__device__ __forceinline__ void decode_fn(const float* __restrict__ W, const float* __restrict__ b,
                                          const float2* cpk, int ind, float* dec, float* dpart) {
    int tid = threadIdx.x;
    if (tid < 240) {
        int seg = tid / 80;
        int d = tid - seg * 80;
        int k0 = (seg == 0) ? 0 : (seg == 1 ? 22 : 43);
        int k1 = (seg == 0) ? 22 : (seg == 1 ? 43 : 64);
        const float* Wb = W + ind + d;
        float a = 0.f;
        for (int k = k0; k < k1; k++) {
            float2 p = cpk[k];
            a = fmaf(p.x, Wb[__float_as_int(p.y)], a);
        }
        dpart[seg * 80 + d] = a;
    }
    __syncthreads();
    if (tid < IDIM)
        dec[tid] = b[ind + tid] + ((dpart[tid] + dpart[80 + tid]) + dpart[160 + tid]);
    __syncthreads();
}

// ---------------- setup 1: Gram (u>0 doubled), bc, ||be||^2 ----------------
__global__ void prep_kernel(const float* __restrict__ We, const float* __restrict__ be) {
    int u = blockIdx.x;
    int warp = threadIdx.x >> 5, lane = threadIdx.x & 31;
    if (u < 80) {
        for (int r = warp; r < 160; r += 8) {
            float s = 0.f;
            if (r < 160 - u) {
                const float* a = We + r * 256;
                const float* b2 = We + (r + u) * 256;
                for (int h = lane; h < 256; h += 32) s = fmaf(a[h], b2[h], s);
            }
            s = warpSum(s);
            if (lane == 0) g_gram[u * 160 + r] = (u > 0) ? 2.f * s : s;
        }
    } else {
        for (int r = warp; r < 160; r += 8) {
            const float* a = We + r * 256;
            float s = 0.f;
            for (int h = lane; h < 256; h += 32) s = fmaf(a[h], be[h], s);
            s = warpSum(s);
            if (lane == 0) g_bcv[r] = s;
        }
        if (warp == 0) {
            float s = 0.f;
            for (int h = lane; h < 256; h += 32) s = fmaf(be[h], be[h], s);
            s = warpSum(s);
            if (lane == 0) g_cbe = s;
        }
    }
}

// ---------------- setup 2: G2 stream (113 rows x 512 cols) ----------------
__global__ void prep2_kernel() {
    int j = blockIdx.x;      // 0..112
    int col = threadIdx.x;   // 0..511
    float v = 0.f;
    if (j < 112) {
        if (col < 400) {
            int p = col / 10, c = col - 10 * p;
            int t0 = c << 3;
            int u = p, u2 = 79 - p;
            int P1 = ((95 - u) >> 4) << 4;
            if (j < P1 + 8) v = g_gram[u * 160 + t0 + j];
            else            v = g_gram[u2 * 160 + t0 + (j - (P1 + 8))];
        } else if (col < 440) {
            int p = col - 400;
            int u = p, u2 = 79 - p;
            int P1 = ((95 - u) >> 4) << 4;
            int P2 = 96 - P1;
            if (j < P1)           v = g_gram[u * 160 + 80 + j];
            else if (j < P1 + P2) v = g_gram[u2 * 160 + 80 + (j - P1)];
        }
    }
    g_G2[j * 512 + col] = v;
}

// ---------------- main per-(b,t) kernel ----------------
__global__ void __launch_bounds__(TPB, 2)
net_main(const float* __restrict__ X, const float* __restrict__ Y,
         const float* __restrict__ We, const float* __restrict__ be,
         const float* __restrict__ Wd, const float* __restrict__ bd,
         const float* __restrict__ Wds, const float* __restrict__ bds) {
    __shared__ __align__(16) float s_part[40 * 81];
    __shared__ __align__(16) float s_xres[240];
    __shared__ __align__(16) float s_xd[240];
    __shared__ __align__(16) float s_z[240];
    __shared__ __align__(16) float s_y[IDIM];
    __shared__ __align__(16) float s_yal[96];
    __shared__ __align__(16) float s_xep[96];
    __shared__ __align__(16) float s_dec[IDIM];
    __shared__ __align__(16) float s_h[HDIM];
    __shared__ __align__(16) u64  s_keys[HDIM];
    __shared__ float s_mps[HDIM], s_mpr[HDIM];
    __shared__ float s_en[NSENC];
    __shared__ float s_lin[NSENC];
    __shared__ float s_sim[NSHIFT];
    __shared__ float s_dpart[240];
    __shared__ float2 s_cpk[CDIM];
    __shared__ float s_wred[NW], s_fb[NW];
    __shared__ int   s_ib[NW];

    int tid = threadIdx.x;
    int n = blockIdx.x;

    for (int i = tid; i < 240; i += TPB) { s_xres[i] = 0.f; s_xd[i] = 0.f; s_z[i] = 0.f; }
    if (tid < 96) { s_yal[tid] = 0.f; s_xep[tid] = 0.f; }
    if (tid < HDIM) { s_mps[tid] = 0.f; s_mpr[tid] = 0.f; }
    __syncthreads();

    if (tid < IDIM) {
        s_xres[80 + tid] = X[n * IDIM + tid];
        s_y[tid] = Y[n * IDIM + tid];
    }
    __syncthreads();

    float cbe = g_cbe;

    float zc = blockSum((tid < IDIM && s_y[tid] == 0.f) ? 1.f : 0.f, s_wred);
    bool smt = (zc > 79.5f);

    float loss_total = 0.f;

    for (int it = 0; it < NIT; ++it) {
        float ny2 = blockSum((tid < IDIM) ? s_y[tid] * s_y[tid] : 0.f, s_wred);
        float ny = sqrtf(ny2);

        // ---- alignment 1: x_res vs y_res ----
        int theta1 = align_fn(s_xres, s_y, ny, s_sim, s_yal, s_fb, s_ib);

        // ---- attention + reverse shift ----
        float yav = (tid < IDIM) ? s_yal[tid] : 0.f;
        float v = (tid < IDIM) ? yav * s_y[tid] : -FLT_MAX;
        float m = blockMax(v, s_wred);
        float e = (tid < IDIM) ? expf(v - m) : 0.f;
        float se = blockSum(e, s_wred);
        if (tid < IDIM) s_z[80 + tid] = yav * (e / se);
        __syncthreads();
        if (tid < IDIM) s_xep[tid] = s_z[159 - theta1 + tid];
        __syncthreads();

        // ---- self branch ----
        int ind_self = encode_fn(We, be, s_xep, s_part, s_lin, s_h, s_en, cbe, s_fb, s_ib);
        float lh_self = hsr_fn(s_h, s_mps, (it == 0), smt, s_keys, s_wred, s_cpk, s_ib);
        decode_fn(Wds, bds, s_cpk, ind_self, s_dec, s_dpart);

        int move1 = abs(theta1 - (IDIM - 1));
        float llc = 0.f;
        if (tid < IDIM && move1 <= ETH_I && s_y[tid] != 0.f) {
            float df = s_dec[tid] - s_xres[80 + tid];
            llc = (df * df) / ((float)move1 + 1.f);
        }
        float ll_self = blockSum(llc, s_wred);

        if (tid < IDIM) s_xd[80 + tid] = s_dec[tid];
        __syncthreads();

        // ---- alignment 2: decoded x_ele vs y_res ----
        int theta2 = align_fn(s_xd, s_y, ny, s_sim, s_yal, s_fb, s_ib);

        // ---- src branch ----
        int ind_src = encode_fn(We, be, s_yal, s_part, s_lin, s_h, s_en, cbe, s_fb, s_ib);
        float lh_src = hsr_fn(s_h, s_mpr, (it == 0), smt, s_keys, s_wred, s_cpk, s_ib);
        decode_fn(Wd, bd, s_cpk, ind_src, s_dec, s_dpart);

        int move2 = abs(theta2 - (IDIM - 1));
        llc = 0.f;
        if (tid < IDIM && move2 <= ETH_I && s_y[tid] != 0.f) {
            float df = s_dec[tid] - s_y[tid];
            llc = (df * df) / ((float)move2 + 1.f);
        }
        float ll_src = blockSum(llc, s_wred);

        loss_total += ll_self + ll_src + lh_self + lh_src;

        // ---- residual update ----
        if (tid < IDIM) {
            s_y[tid]         -= s_dec[tid];
            s_xres[80 + tid] -= s_xd[80 + tid];
        }
        __syncthreads();
    }

    if (tid == 0) g_partial[n] = loss_total;
}

// ---------------- deterministic final reduction ----------------
__global__ void net_reduce(float* __restrict__ out) {
    __shared__ float buf[8];
    float s = 0.f;
    for (int i = threadIdx.x; i < NPOS; i += 256) s += g_partial[i];
    s = warpSum(s);
    int w = threadIdx.x >> 5, l = threadIdx.x & 31;
    if (l == 0) buf[w] = s;
    __syncthreads();
    if (threadIdx.x == 0) {
        float t = 0.f;
#pragma unroll
        for (int i = 0; i < 8; i++) t += buf[i];
        out[0] = t * 0.25f;
    }
}

extern "C" void kernel_launch(void* const* d_in, const int* in_sizes, int n_in,
                              void* d_out, int out_size) {
    const float* X   = (const float*)d_in[0];
    const float* Y   = (const float*)d_in[1];
    const float* We  = (const float*)d_in[2];
    const float* be  = (const float*)d_in[3];
    const float* Wd  = (const float*)d_in[4];
    const float* bdv = (const float*)d_in[5];
    const float* Wds = (const float*)d_in[6];
    const float* bds = (const float*)d_in[7];
    float* out = (float*)d_out;

    prep_kernel<<<81, 256>>>(We, be);
    prep2_kernel<<<113, 512>>>();
    net_main<<<NPOS, TPB>>>(X, Y, We, be, Wd, bdv, Wds, bds);
    net_reduce<<<1, 256>>>(out);
}

// round 10
// speedup vs baseline: 1.4632x; 1.4632x over previous
#include <cuda_runtime.h>
#include <math.h>
#include <float.h>

#define Bb 8
#define Tt 256
#define NPOS (Bb*Tt)     // 2048
#define IDIM 80
#define HDIM 256
#define CDIM 64
#define NIT 4
#define TPB 256
#define NSHIFT 159
#define NSENC 81
#define ETH_I 40
#define GW 192           // padded gram row width

typedef unsigned long long u64;

__device__ float g_partial[NPOS];
__device__ float g_gram[80 * GW];    // u>=1 rows PRE-DOUBLED; zero beyond 160-u; padded to 192
__device__ float g_bcv[160];
__device__ float g_cbe;
__device__ float g_G2[113 * 512];    // access-order transposed gram stream (440 used cols)

// ---------------- f32x2 helpers ----------------
__device__ __forceinline__ u64 dup2(float x) {
    u64 r; asm("mov.b64 %0, {%1, %1};" : "=l"(r) : "f"(x)); return r;
}
__device__ __forceinline__ u64 pack2(float lo, float hi) {
    u64 r; asm("mov.b64 %0, {%1, %2};" : "=l"(r) : "f"(lo), "f"(hi)); return r;
}
__device__ __forceinline__ void fma2(u64& acc, u64 a, u64 b) {
    asm("fma.rn.f32x2 %0, %1, %2, %0;" : "+l"(acc) : "l"(a), "l"(b));
}
__device__ __forceinline__ void unpk(u64 v, float& lo, float& hi) {
    asm("mov.b64 {%0, %1}, %2;" : "=f"(lo), "=f"(hi) : "l"(v));
}

// ---------------- reductions (deterministic, 2-sync) ----------------
__device__ __forceinline__ float warpSum(float v) {
#pragma unroll
    for (int o = 16; o > 0; o >>= 1) v += __shfl_down_sync(0xffffffffu, v, o);
    return v;
}

__device__ __forceinline__ float blockSum(float v, float* buf) {
    v = warpSum(v);
    int w = threadIdx.x >> 5, l = threadIdx.x & 31;
    if (l == 0) buf[w] = v;
    __syncthreads();
    float s = 0.f;
#pragma unroll
    for (int i = 0; i < 8; i++) s += buf[i];
    __syncthreads();
    return s;
}

__device__ __forceinline__ float blockMax(float v, float* buf) {
#pragma unroll
    for (int o = 16; o > 0; o >>= 1) v = fmaxf(v, __shfl_down_sync(0xffffffffu, v, o));
    int w = threadIdx.x >> 5, l = threadIdx.x & 31;
    if (l == 0) buf[w] = v;
    __syncthreads();
    float s = buf[0];
#pragma unroll
    for (int i = 1; i < 8; i++) s = fmaxf(s, buf[i]);
    __syncthreads();
    return s;
}

__device__ __forceinline__ int blockArgmax(const float* arr, int L, float* fb, int* ib) {
    float bv = -FLT_MAX; int bi = 0x7FFFFFFF;
    for (int i = threadIdx.x; i < L; i += TPB) {
        float v = arr[i];
        if (v > bv || (v == bv && i < bi)) { bv = v; bi = i; }
    }
#pragma unroll
    for (int o = 16; o > 0; o >>= 1) {
        float ov = __shfl_down_sync(0xffffffffu, bv, o);
        int   oi = __shfl_down_sync(0xffffffffu, bi, o);
        if (ov > bv || (ov == bv && oi < bi)) { bv = ov; bi = oi; }
    }
    int w = threadIdx.x >> 5, l = threadIdx.x & 31;
    if (l == 0) { fb[w] = bv; ib[w] = bi; }
    __syncthreads();
    float v = fb[0]; int j = ib[0];
#pragma unroll
    for (int i = 1; i < 8; i++)
        if (fb[i] > v || (fb[i] == v && ib[i] < j)) { v = fb[i]; j = ib[i]; }
    __syncthreads();
    return j;
}

// ---------------- alignment ----------------
__device__ __forceinline__ int align_fn(const float* xpad, const float* yr, float ny,
                                        float* sim, float* yal, float* fb, int* ib) {
    int s = threadIdx.x;
    if (s < NSHIFT) {
        float num = 0.f, nx2 = 0.f;
        const float* xp = xpad + s + 1;
#pragma unroll 8
        for (int w = 0; w < 80; w++) {
            float xv = xp[w];
            num = fmaf(xv, yr[w], num);
            nx2 = fmaf(xv, xv, nx2);
        }
        sim[s] = num / (sqrtf(nx2) * ny + 1e-6f);
    }
    __syncthreads();
    int theta = blockArgmax(sim, NSHIFT, fb, ib);
    if (threadIdx.x < IDIM)
        yal[threadIdx.x] = xpad[theta + (int)threadIdx.x + 1];
    __syncthreads();
    return theta;
}

// ---------------- corr segment: 4 paired-t accumulators (8 outputs, FFMA2) ----------------
__device__ __forceinline__ void enc_seg8(const float* inp, const float* ipu,
                                         const float* __restrict__ gbase, int joff,
                                         u64* acc2, int nblocks) {
    const float* gp = gbase + joff * 512;
    u64 E[4], O[4];
    float c;
    {
        float prev = *gp; gp += 512;
#pragma unroll
        for (int k = 0; k < 4; k++) {
            float a = *gp; gp += 512;
            float b = *gp; gp += 512;
            E[k] = pack2(prev, a);
            O[k] = pack2(a, b);
            prev = b;
        }
        c = prev;
    }
    for (int b = 0; b < nblocks; b++) {
        const float* ia = inp + (b << 4);
        const float* ib2 = ipu + (b << 4);
#pragma unroll
        for (int i = 0; i < 16; i++) {
            float qv = ia[i] * ib2[i];
            u64 qd = dup2(qv);
            if ((i & 1) == 0) {
#pragma unroll
                for (int m = 0; m < 4; m++)
                    fma2(acc2[m], qd, E[((i >> 1) + m) & 3]);
                float n = *gp; gp += 512;
                E[(i >> 1) & 3] = pack2(c, n);
                c = n;
            } else {
#pragma unroll
                for (int m = 0; m < 4; m++)
                    fma2(acc2[m], qd, O[((i >> 1) + m) & 3]);
                float n = *gp; gp += 512;
                O[(i >> 1) & 3] = pack2(c, n);
                c = n;
            }
        }
    }
}

// one corr item for column col (pair-chunk if <400, t=80 scalar-as-8wide otherwise)
__device__ __forceinline__ void corr_item(int col, const float* inp, float* part) {
    int p, t0;
    if (col < 400) { p = col / 10; t0 = (col - 10 * p) << 3; }
    else           { p = col - 400; t0 = 80; }
    int u = p, u2 = 79 - p;
    int P1 = ((95 - u) >> 4) << 4;
    u64 acc2[4];
#pragma unroll
    for (int m = 0; m < 4; m++) acc2[m] = 0ull;
    const float* gbase = g_G2 + col;
    enc_seg8(inp, inp + u,  gbase, 0,      acc2, P1 >> 4);
    enc_seg8(inp, inp + u2, gbase, P1 + 8, acc2, (96 - P1) >> 4);
    if (col < 400) {
        float* pp = part + p * 81 + t0;
#pragma unroll
        for (int m = 0; m < 4; m++) {
            float lo, hi; unpk(acc2[m], lo, hi);
            pp[2 * m]     = lo;
            pp[2 * m + 1] = hi;
        }
    } else {
        float lo, hi; unpk(acc2[0], lo, hi);
        part[p * 81 + 80] = lo;
    }
}

// ---------------- encoder via Gram energies ----------------
__device__ __noinline__ int encode_fn(const float* __restrict__ We,
                                      const float* __restrict__ be,
                                      const float* inp, float* part, float* lin,
                                      float* s_h, float* en, float cbe,
                                      float* fb, int* ib) {
    int tid = threadIdx.x;

    if (tid < 220) {
        corr_item(tid,       inp, part);
        corr_item(tid + 220, inp, part);
    } else if (tid >= 224) {
        int k = tid - 224;
#pragma unroll
        for (int r = 0; r < 3; r++) {
            int t = k + (r << 5);
            if (t < 81) {
                float l = 0.f;
                const float* bc = g_bcv + t;
#pragma unroll 4
                for (int d = 0; d < 80; d++) l = fmaf(inp[d], bc[d], l);
                lin[t] = l;
            }
        }
    }
    __syncthreads();

    if (tid <= 80) {
        int t = tid;
        float s = 0.f;
#pragma unroll 4
        for (int p = 0; p < 40; p++) s += part[p * 81 + t];
        en[80 - t] = cbe + 2.f * lin[t] + s;
    }
    __syncthreads();

    int ind = blockArgmax(en, NSENC, fb, ib);

    // recompute H[ind] exactly (validated FMA order)
    {
        const float* wp = We + (80 - ind) * 256 + tid;
        float a0 = 0.f, a1 = 0.f, a2 = 0.f, a3 = 0.f;
#pragma unroll 4
        for (int d = 0; d < 80; d += 4) {
            a0 = fmaf(inp[d],     wp[(d)     * 256], a0);
            a1 = fmaf(inp[d + 1], wp[(d + 1) * 256], a1);
            a2 = fmaf(inp[d + 2], wp[(d + 2) * 256], a2);
            a3 = fmaf(inp[d + 3], wp[(d + 3) * 256], a3);
        }
        s_h[tid] = be[tid] + ((a0 + a1) + (a2 + a3));
    }
    __syncthreads();
    return ind;
}

// ---------------- HSR via warp-sorted rank ----------------
__device__ __forceinline__ u64 warp_sort32(u64 key) {
    int lane = threadIdx.x & 31;
#pragma unroll
    for (int k = 2; k <= 32; k <<= 1) {
#pragma unroll
        for (int j = k >> 1; j > 0; j >>= 1) {
            u64 other = __shfl_xor_sync(0xffffffffu, key, j);
            bool up = ((lane & k) == 0);
            bool lower = ((lane & j) == 0);
            bool takeMin = (up == lower);
            u64 mn = (key < other) ? key : other;
            u64 mx = (key < other) ? other : key;
            key = takeMin ? mn : mx;
        }
    }
    return key;
}

__device__ __forceinline__ int rank_sorted(u64 key, const u64* lists) {
    int cle = 0;
#pragma unroll
    for (int w = 0; w < 8; w++) {
        const u64* L = lists + (w << 5);
        int cnt = 0;
#pragma unroll
        for (int step = 16; step > 0; step >>= 1) {
            int t = cnt + step;
            if (t <= 32 && L[t - 1] <= key) cnt = t;
        }
        if (cnt < 32 && L[cnt] <= key) cnt++;
        cle += cnt;
    }
    return 256 - cle;
}

__device__ __forceinline__ u64 make_key(float hq, int tid) {
    return ((u64)__float_as_uint(hq) << 32) | (u64)(unsigned)(255 - tid);
}

__device__ __forceinline__ float hsr_fn(const float* hin, float* mp, bool first, bool smt,
                                        u64* lists, float* wred, float2* cpk, int* ibuf) {
    int tid = threadIdx.x, lane = tid & 31, wid = tid >> 5;
    float h = hin[tid];
    u64 key = make_key(h * h, tid);
    u64 skey = warp_sort32(key);
    lists[(wid << 5) + lane] = skey;
    __syncthreads();
    bool cur = rank_sorted(key, lists) < CDIM;
    float loss = 0.f;
    bool sel; float hval;
    if (first) {
        mp[tid] = cur ? 1.f : 0.f;
        sel = cur; hval = h;
        __syncthreads();
    } else {
        bool prev = mp[tid] > 0.f;
        loss = blockSum((prev && cur && !smt) ? h * h : 0.f, wred);
        float h2 = prev ? 0.f : h;
        u64 key2 = make_key(h2 * h2, tid);
        u64 skey2 = warp_sort32(key2);
        lists[(wid << 5) + lane] = skey2;
        __syncthreads();
        bool cur2 = rank_sorted(key2, lists) < CDIM;
        if (cur2) mp[tid] += 1.f;
        sel = cur2; hval = h2;
    }
    unsigned bal = __ballot_sync(0xffffffffu, sel);
    if (lane == 0) ibuf[wid] = __popc(bal);
    __syncthreads();
    int base = 0;
#pragma unroll
    for (int w = 0; w < 8; w++) base += (w < wid) ? ibuf[w] : 0;
    int pos = base + __popc(bal & ((1u << lane) - 1u));
    if (sel) cpk[pos] = make_float2(hval, __int_as_float(tid * 160));
    __syncthreads();
    return loss;
}

// ---------------- sparse decode ----------------
__device__ __forceinline__ void decode_fn(const float* __restrict__ W, const float* __restrict__ b,
                                          const float2* cpk, int ind, float* dec, float* dpart) {
    int tid = threadIdx.x;
    if (tid < 240) {
        int seg = tid / 80;
        int d = tid - seg * 80;
        int k0 = (seg == 0) ? 0 : (seg == 1 ? 22 : 43);
        int k1 = (seg == 0) ? 22 : (seg == 1 ? 43 : 64);
        const float* Wb = W + ind + d;
        float a = 0.f;
        for (int k = k0; k < k1; k++) {
            float2 p = cpk[k];
            a = fmaf(p.x, Wb[__float_as_int(p.y)], a);
        }
        dpart[seg * 80 + d] = a;
    }
    __syncthreads();
    if (tid < IDIM)
        dec[tid] = b[ind + tid] + ((dpart[tid] + dpart[80 + tid]) + dpart[160 + tid]);
    __syncthreads();
}

// ---------------- setup 1: Gram (u>0 doubled, rows padded to GW), bc, ||be||^2 ----------------
__global__ void prep_kernel(const float* __restrict__ We, const float* __restrict__ be) {
    int u = blockIdx.x;
    int warp = threadIdx.x >> 5, lane = threadIdx.x & 31;
    if (u < 80) {
        for (int r = warp; r < GW; r += 8) {
            float s = 0.f;
            if (r < 160 - u) {
                const float* a = We + r * 256;
                const float* b2 = We + (r + u) * 256;
                for (int h = lane; h < 256; h += 32) s = fmaf(a[h], b2[h], s);
            }
            s = warpSum(s);
            if (lane == 0) g_gram[u * GW + r] = (u > 0) ? 2.f * s : s;
        }
    } else {
        for (int r = warp; r < 160; r += 8) {
            const float* a = We + r * 256;
            float s = 0.f;
            for (int h = lane; h < 256; h += 32) s = fmaf(a[h], be[h], s);
            s = warpSum(s);
            if (lane == 0) g_bcv[r] = s;
        }
        if (warp == 0) {
            float s = 0.f;
            for (int h = lane; h < 256; h += 32) s = fmaf(be[h], be[h], s);
            s = warpSum(s);
            if (lane == 0) g_cbe = s;
        }
    }
}

// ---------------- setup 2: G2 stream (113 rows x 512 cols, 440 uniform items) ----------------
__global__ void prep2_kernel() {
    int j = blockIdx.x;      // 0..112
    int col = threadIdx.x;   // 0..511
    float v = 0.f;
    if (col < 440) {
        int p, t0;
        if (col < 400) { p = col / 10; t0 = (col - 10 * p) << 3; }
        else           { p = col - 400; t0 = 80; }
        int u = p, u2 = 79 - p;
        int P1 = ((95 - u) >> 4) << 4;
        if (j < P1 + 8) v = g_gram[u * GW + t0 + j];
        else            v = g_gram[u2 * GW + t0 + (j - (P1 + 8))];
    }
    g_G2[j * 512 + col] = v;
}

// ---------------- main per-(b,t) kernel ----------------
__global__ void __launch_bounds__(TPB, 4)
net_main(const float* __restrict__ X, const float* __restrict__ Y,
         const float* __restrict__ We, const float* __restrict__ be,
         const float* __restrict__ Wd, const float* __restrict__ bd,
         const float* __restrict__ Wds, const float* __restrict__ bds) {
    __shared__ __align__(16) float s_part[40 * 81];
    __shared__ __align__(16) float s_xres[240];
    __shared__ __align__(16) float s_xd[240];
    __shared__ __align__(16) float s_z[240];
    __shared__ __align__(16) float s_y[IDIM];
    __shared__ __align__(16) float s_yal[96];
    __shared__ __align__(16) float s_xep[96];
    __shared__ __align__(16) float s_dec[IDIM];
    __shared__ __align__(16) float s_h[HDIM];
    __shared__ __align__(16) u64  s_keys[HDIM];
    __shared__ float s_mps[HDIM], s_mpr[HDIM];
    __shared__ float s_en[NSENC];
    __shared__ float s_lin[NSENC];
    __shared__ float s_sim[NSHIFT];
    __shared__ float s_dpart[240];
    __shared__ float2 s_cpk[CDIM];
    __shared__ float s_wred[8], s_fb[8];
    __shared__ int   s_ib[8];

    int tid = threadIdx.x;
    int n = blockIdx.x;

    for (int i = tid; i < 240; i += TPB) { s_xres[i] = 0.f; s_xd[i] = 0.f; s_z[i] = 0.f; }
    if (tid < 96) { s_yal[tid] = 0.f; s_xep[tid] = 0.f; }
    s_mps[tid] = 0.f; s_mpr[tid] = 0.f;
    __syncthreads();

    if (tid < IDIM) {
        s_xres[80 + tid] = X[n * IDIM + tid];
        s_y[tid] = Y[n * IDIM + tid];
    }
    __syncthreads();

    float cbe = g_cbe;

    float zc = blockSum((tid < IDIM && s_y[tid] == 0.f) ? 1.f : 0.f, s_wred);
    bool smt = (zc > 79.5f);

    float loss_total = 0.f;

    for (int it = 0; it < NIT; ++it) {
        float ny2 = blockSum((tid < IDIM) ? s_y[tid] * s_y[tid] : 0.f, s_wred);
        float ny = sqrtf(ny2);

        // ---- alignment 1: x_res vs y_res ----
        int theta1 = align_fn(s_xres, s_y, ny, s_sim, s_yal, s_fb, s_ib);

        // ---- attention + reverse shift ----
        float yav = (tid < IDIM) ? s_yal[tid] : 0.f;
        float v = (tid < IDIM) ? yav * s_y[tid] : -FLT_MAX;
        float m = blockMax(v, s_wred);
        float e = (tid < IDIM) ? expf(v - m) : 0.f;
        float se = blockSum(e, s_wred);
        if (tid < IDIM) s_z[80 + tid] = yav * (e / se);
        __syncthreads();
        if (tid < IDIM) s_xep[tid] = s_z[159 - theta1 + tid];
        __syncthreads();

        // ---- self branch ----
        int ind_self = encode_fn(We, be, s_xep, s_part, s_lin, s_h, s_en, cbe, s_fb, s_ib);
        float lh_self = hsr_fn(s_h, s_mps, (it == 0), smt, s_keys, s_wred, s_cpk, s_ib);
        decode_fn(Wds, bds, s_cpk, ind_self, s_dec, s_dpart);

        int move1 = abs(theta1 - (IDIM - 1));
        float llc = 0.f;
        if (tid < IDIM && move1 <= ETH_I && s_y[tid] != 0.f) {
            float df = s_dec[tid] - s_xres[80 + tid];
            llc = (df * df) / ((float)move1 + 1.f);
        }
        float ll_self = blockSum(llc, s_wred);

        if (tid < IDIM) s_xd[80 + tid] = s_dec[tid];
        __syncthreads();

        // ---- alignment 2: decoded x_ele vs y_res ----
        int theta2 = align_fn(s_xd, s_y, ny, s_sim, s_yal, s_fb, s_ib);

        // ---- src branch ----
        int ind_src = encode_fn(We, be, s_yal, s_part, s_lin, s_h, s_en, cbe, s_fb, s_ib);
        float lh_src = hsr_fn(s_h, s_mpr, (it == 0), smt, s_keys, s_wred, s_cpk, s_ib);
        decode_fn(Wd, bd, s_cpk, ind_src, s_dec, s_dpart);

        int move2 = abs(theta2 - (IDIM - 1));
        llc = 0.f;
        if (tid < IDIM && move2 <= ETH_I && s_y[tid] != 0.f) {
            float df = s_dec[tid] - s_y[tid];
            llc = (df * df) / ((float)move2 + 1.f);
        }
        float ll_src = blockSum(llc, s_wred);

        loss_total += ll_self + ll_src + lh_self + lh_src;

        // ---- residual update ----
        if (tid < IDIM) {
            s_y[tid]         -= s_dec[tid];
            s_xres[80 + tid] -= s_xd[80 + tid];
        }
        __syncthreads();
    }

    if (tid == 0) g_partial[n] = loss_total;
}

// ---------------- deterministic final reduction ----------------
__global__ void net_reduce(float* __restrict__ out) {
    __shared__ float buf[8];
    float s = 0.f;
    for (int i = threadIdx.x; i < NPOS; i += 256) s += g_partial[i];
    s = warpSum(s);
    int w = threadIdx.x >> 5, l = threadIdx.x & 31;
    if (l == 0) buf[w] = s;
    __syncthreads();
    if (threadIdx.x == 0) {
        float t = 0.f;
#pragma unroll
        for (int i = 0; i < 8; i++) t += buf[i];
        out[0] = t * 0.25f;
    }
}

extern "C" void kernel_launch(void* const* d_in, const int* in_sizes, int n_in,
                              void* d_out, int out_size) {
    const float* X   = (const float*)d_in[0];
    const float* Y   = (const float*)d_in[1];
    const float* We  = (const float*)d_in[2];
    const float* be  = (const float*)d_in[3];
    const float* Wd  = (const float*)d_in[4];
    const float* bdv = (const float*)d_in[5];
    const float* Wds = (const float*)d_in[6];
    const float* bds = (const float*)d_in[7];
    float* out = (float*)d_out;

    prep_kernel<<<81, 256>>>(We, be);
    prep2_kernel<<<113, 512>>>();
    net_main<<<NPOS, TPB>>>(X, Y, We, be, Wd, bdv, Wds, bds);
    net_reduce<<<1, 256>>>(out);
}